// round 12
// baseline (speedup 1.0000x reference)
#include <cuda_runtime.h>
#include <cuda_fp16.h>
#include <cstdint>

// ============================ config ============================
#define K_DIM 1024
#define N_DIM 1024
#define BM 128
#define BN 128
#define BK 64
#define KTILES (K_DIM / BK)   // 16
#define THREADS 128

#define A_STAGE (BM * BK * 2)                 // 16384 B
#define B_STAGE (BN * BK * 2)                 // 16384 B
#define SMEM_TOTAL (2 * (A_STAGE + B_STAGE))  // 65536 B (2-stage)

#define NC_BLOCKS 32768   // convert blocks in prepass (65536*1024/8/256)

// static scratch (allocation-free rule: __device__ globals)
__device__ __half g_xh[(size_t)65536 * K_DIM];   // x converted to fp16
__device__ __half g_Wt[(size_t)N_DIM * K_DIM];   // W transposed to (N,K) fp16

// ============================ helpers ============================
__device__ __forceinline__ uint32_t smem_u32(const void* p) {
    uint32_t a;
    asm("{ .reg .u64 t; cvta.to.shared.u64 t, %1; cvt.u32.u64 %0, t; }"
        : "=r"(a) : "l"(p));
    return a;
}

__device__ __forceinline__ void cp_async16(uint32_t dst, const void* src) {
    asm volatile("cp.async.cg.shared.global [%0], [%1], 16;" :: "r"(dst), "l"(src));
}
#define CP_COMMIT() asm volatile("cp.async.commit_group;" ::: "memory")
#define CP_WAIT(n)  asm volatile("cp.async.wait_group %0;" :: "n"(n) : "memory")

__device__ __forceinline__ void ldsm_x4(uint32_t& r0, uint32_t& r1,
                                        uint32_t& r2, uint32_t& r3, uint32_t addr) {
    asm volatile("ldmatrix.sync.aligned.m8n8.x4.shared.b16 {%0,%1,%2,%3}, [%4];"
                 : "=r"(r0), "=r"(r1), "=r"(r2), "=r"(r3) : "r"(addr));
}

__device__ __forceinline__ void mma16816(float* d, const uint32_t* a,
                                         uint32_t b0, uint32_t b1) {
    asm volatile(
        "mma.sync.aligned.m16n8k16.row.col.f32.f16.f16.f32 "
        "{%0,%1,%2,%3}, {%4,%5,%6,%7}, {%8,%9}, {%0,%1,%2,%3};"
        : "+f"(d[0]), "+f"(d[1]), "+f"(d[2]), "+f"(d[3])
        : "r"(a[0]), "r"(a[1]), "r"(a[2]), "r"(a[3]), "r"(b0), "r"(b1));
}

// sigmoid via single-MUFU tanh.approx: sig(v) = 0.5*tanh(0.5v) + 0.5
__device__ __forceinline__ float fsig(float v) {
    float t;
    asm("tanh.approx.f32 %0, %1;" : "=f"(t) : "f"(v * 0.5f));
    return fmaf(0.5f, t, 0.5f);
}

// ============================ merged pre-pass ============================
__global__ void prepass_kernel(const float* __restrict__ x,
                               const float* __restrict__ W) {
    if (blockIdx.x < NC_BLOCKS) {
        size_t i = ((size_t)blockIdx.x * 256 + threadIdx.x) * 8;
        float4 f0 = *reinterpret_cast<const float4*>(x + i);
        float4 f1 = *reinterpret_cast<const float4*>(x + i + 4);
        __half2 h0 = __floats2half2_rn(f0.x, f0.y);
        __half2 h1 = __floats2half2_rn(f0.z, f0.w);
        __half2 h2 = __floats2half2_rn(f1.x, f1.y);
        __half2 h3 = __floats2half2_rn(f1.z, f1.w);
        uint4 o;
        o.x = *reinterpret_cast<uint32_t*>(&h0);
        o.y = *reinterpret_cast<uint32_t*>(&h1);
        o.z = *reinterpret_cast<uint32_t*>(&h2);
        o.w = *reinterpret_cast<uint32_t*>(&h3);
        *reinterpret_cast<uint4*>(&g_xh[i]) = o;
    } else {
        __shared__ float t[32][33];
        int bidx = blockIdx.x - NC_BLOCKS;
        int bx = bidx & 31;        // n tile
        int by = bidx >> 5;        // k tile
        int tx = threadIdx.x & 31;
        int ty = threadIdx.x >> 5; // 0..7
        int n = bx * 32 + tx;
        int k = by * 32 + ty;
#pragma unroll
        for (int i = 0; i < 4; ++i)
            t[ty + i * 8][tx] = W[(size_t)(k + i * 8) * N_DIM + n];
        __syncthreads();
        int n2 = bx * 32 + ty;
        int k2 = by * 32 + tx;
#pragma unroll
        for (int i = 0; i < 4; ++i)
            g_Wt[(size_t)(n2 + i * 8) * K_DIM + k2] =
                __float2half(t[tx][ty + i * 8]);
    }
}

// ============================ main fused kernel ============================
// 4 warps in 2x2, warp tile 64x64 (acc 128 regs); 3 CTAs/SM (12 warps),
// 2-stage pipeline, 64KB smem/CTA. B fragments are STREAMED (one ldsm.x4
// live at a time) so the working set fits the 168-reg cap without spills:
// live ~= acc 128 + A frags 16 + B frag 4 + addressing.
__global__ __launch_bounds__(THREADS, 3)
void fused_gemm_gn_swish_kernel(const float* __restrict__ bias,
                                const float* __restrict__ mw,
                                float* __restrict__ out) {
    extern __shared__ char smem[];
    uint32_t sb = smem_u32(smem);
    const int tid  = threadIdx.x;
    const int lane = tid & 31;
    const int wid  = tid >> 5;
    const int wm   = wid >> 1;   // 0..1  (M warp row, 64 rows)
    const int wn   = wid & 1;    // 0..1  (N warp col, 64 cols = two GN groups)
    const int m0   = blockIdx.y * BM;
    const int n0   = blockIdx.x * BN;

    uint32_t sA = sb;                      // 2 x 16KB
    uint32_t sB = sb + 2 * A_STAGE;        // 2 x 16KB

    // ---- load addressing: base offsets; chunk i adds immediates ----
    const int r0 = tid >> 3, c0 = tid & 7;
    const uint32_t s_off = (uint32_t)(r0 * 128 + (((c0 ^ (r0 & 7))) << 4));
    const uint32_t g_off = (uint32_t)(r0 * K_DIM + c0 * 8);

    const __half* ag = g_xh + (size_t)m0 * K_DIM + g_off;
    const __half* bg = g_Wt + (size_t)n0 * K_DIM + g_off;

    // prologue: fill stage 0 (A: 8 chunks of 16 rows; B: 8 chunks)
#pragma unroll
    for (int i = 0; i < 8; ++i) cp_async16(sA + s_off + i * 2048, ag + i * 16 * K_DIM);
#pragma unroll
    for (int i = 0; i < 8; ++i) cp_async16(sB + s_off + i * 2048, bg + i * 16 * K_DIM);
    CP_COMMIT();
    ag += BK; bg += BK;

    float acc[4][8][4];
#pragma unroll
    for (int i = 0; i < 4; ++i)
#pragma unroll
        for (int j = 0; j < 8; ++j)
#pragma unroll
            for (int e = 0; e < 4; ++e) acc[i][j][e] = 0.0f;

    // ldmatrix lane addressing
    const int lrow   = lane & 15;
    const int lchunk = lane >> 4;
    const uint32_t aRow = (uint32_t)(wm * 64 + lrow) * 128;
    const uint32_t bRow = (uint32_t)(wn * 64 + lrow) * 128;
    uint32_t soff[4];
#pragma unroll
    for (int ks = 0; ks < 4; ++ks)
        soff[ks] = (uint32_t)(((ks * 2 + lchunk) ^ (lrow & 7)) << 4);

    for (int kt = 0; kt < KTILES; ++kt) {
        CP_WAIT(0);          // stage kt resident
        __syncthreads();     // other buffer free; loads visible

        // issue stage kt+1 into the other buffer
        if (kt + 1 < KTILES) {
            uint32_t dA = sA + ((kt + 1) & 1) * A_STAGE + s_off;
            uint32_t dB = sB + ((kt + 1) & 1) * B_STAGE + s_off;
#pragma unroll
            for (int i = 0; i < 8; ++i) cp_async16(dA + i * 2048, ag + i * 16 * K_DIM);
#pragma unroll
            for (int i = 0; i < 8; ++i) cp_async16(dB + i * 2048, bg + i * 16 * K_DIM);
            CP_COMMIT();
            ag += BK; bg += BK;
        }

        uint32_t aB = sA + (kt & 1) * A_STAGE + aRow;
        uint32_t bB = sB + (kt & 1) * B_STAGE + bRow;
#pragma unroll
        for (int ks = 0; ks < 4; ++ks) {
            // A fragments resident for this ks (16 regs)
            uint32_t a[4][4];
#pragma unroll
            for (int mi = 0; mi < 4; ++mi)
                ldsm_x4(a[mi][0], a[mi][1], a[mi][2], a[mi][3],
                        aB + mi * (16 * 128) + soff[ks]);
            // B streamed: one ldsm.x4 (4 regs) live at a time, 8 mma per chunk
#pragma unroll
            for (int p = 0; p < 4; ++p) {
                uint32_t bq0, bq1, bq2, bq3;
                ldsm_x4(bq0, bq1, bq2, bq3, bB + p * (16 * 128) + soff[ks]);
                // bq0=n(lo8) k0-7, bq1=n(hi8) k0-7, bq2=lo k8-15, bq3=hi k8-15
#pragma unroll
                for (int mi = 0; mi < 4; ++mi) {
                    mma16816(acc[mi][2 * p],     a[mi], bq0, bq2);
                    mma16816(acc[mi][2 * p + 1], a[mi], bq1, bq3);
                }
            }
        }
    }

    // -------- fused epilogue: bias + GroupNorm(32ch) + swish * w * swish --------
    const int q  = lane >> 2;
    const int qt = lane & 3;
    const float inv32 = 1.0f / 32.0f;
    const float* bp = bias + n0 + wn * 64 + qt * 2;
    const float* wp = mw   + n0 + wn * 64 + qt * 2;

#pragma unroll
    for (int mi = 0; mi < 4; ++mi) {
#pragma unroll
        for (int half = 0; half < 2; ++half) {
            int row = m0 + wm * 64 + mi * 16 + half * 8 + q;
            float* op = out + (size_t)row * N_DIM + n0 + wn * 64;
#pragma unroll
            for (int g2 = 0; g2 < 2; ++g2) {     // two 32-ch groups per warp tile
                float v[8];
                float sum = 0.0f, ssq = 0.0f;
#pragma unroll
                for (int nj = 0; nj < 4; ++nj) {
                    int ni = g2 * 4 + nj;
                    float2 bv = *reinterpret_cast<const float2*>(bp + ni * 8);
#pragma unroll
                    for (int e = 0; e < 2; ++e) {
                        float val = acc[mi][ni][half * 2 + e] + ((e == 0) ? bv.x : bv.y);
                        v[nj * 2 + e] = val;
                        sum += val;
                        ssq = fmaf(val, val, ssq);
                    }
                }
                sum += __shfl_xor_sync(0xffffffffu, sum, 1);
                ssq += __shfl_xor_sync(0xffffffffu, ssq, 1);
                sum += __shfl_xor_sync(0xffffffffu, sum, 2);
                ssq += __shfl_xor_sync(0xffffffffu, ssq, 2);
                float mean = sum * inv32;
                float var  = fmaf(ssq, inv32, -mean * mean);
                float rstd = rsqrtf(var + 1e-5f);

#pragma unroll
                for (int nj = 0; nj < 4; ++nj) {
                    int ni = g2 * 4 + nj;
                    float2 wv = *reinterpret_cast<const float2*>(wp + ni * 8);
                    float2 o;
#pragma unroll
                    for (int e = 0; e < 2; ++e) {
                        float nv = (v[nj * 2 + e] - mean) * rstd;
                        float s  = nv * fsig(nv);
                        float mm = s * ((e == 0) ? wv.x : wv.y);
                        float ov = mm * fsig(mm);
                        if (e == 0) o.x = ov; else o.y = ov;
                    }
                    __stcs(reinterpret_cast<float2*>(op + ni * 8 + qt * 2), o);
                }
            }
        }
    }
}

// ============================ launch ============================
extern "C" void kernel_launch(void* const* d_in, const int* in_sizes, int n_in,
                              void* d_out, int out_size) {
    const float* x  = (const float*)d_in[0];
    const float* W  = (const float*)d_in[1];
    const float* b  = (const float*)d_in[2];
    const float* mw = (const float*)d_in[3];
    float* out = (float*)d_out;

    const size_t M = (size_t)in_sizes[0] / K_DIM;   // 65536

    // 1) merged pre-pass: x -> fp16 and W -> Wt fp16
    prepass_kernel<<<NC_BLOCKS + (N_DIM / 32) * (K_DIM / 32), 256>>>(x, W);

    // 2) fused GEMM + bias + GroupNorm + Swish chain (3 CTAs/SM, streamed B frags)
    cudaFuncSetAttribute(fused_gemm_gn_swish_kernel,
                         cudaFuncAttributeMaxDynamicSharedMemorySize, SMEM_TOTAL);
    dim3 grid(N_DIM / BN, (unsigned)(M / BM));  // x fastest: 8 N-tiles share an A band in L2
    fused_gemm_gn_swish_kernel<<<grid, THREADS, SMEM_TOTAL>>>(b, mw, out);
}

// round 13
// speedup vs baseline: 1.1744x; 1.1744x over previous
#include <cuda_runtime.h>
#include <cuda_fp16.h>
#include <cstdint>

// ============================ config ============================
#define K_DIM 1024
#define N_DIM 1024
#define BM 128
#define BN 128
#define BK 64
#define KTILES (K_DIM / BK)   // 16
#define THREADS 128

#define A_STAGE (BM * BK * 2)                 // 16384 B
#define B_STAGE (BN * BK * 2)                 // 16384 B
#define SMEM_TOTAL (2 * (A_STAGE + B_STAGE))  // 65536 B (2-stage)

#define NC_BLOCKS 32768   // convert blocks in prepass (65536*1024/8/256)

// static scratch (allocation-free rule: __device__ globals)
__device__ __half g_xh[(size_t)65536 * K_DIM];   // x converted to fp16
__device__ __half g_Wt[(size_t)N_DIM * K_DIM];   // W transposed to (N,K) fp16

// ============================ helpers ============================
__device__ __forceinline__ uint32_t smem_u32(const void* p) {
    uint32_t a;
    asm("{ .reg .u64 t; cvta.to.shared.u64 t, %1; cvt.u32.u64 %0, t; }"
        : "=r"(a) : "l"(p));
    return a;
}

__device__ __forceinline__ void cp_async16(uint32_t dst, const void* src) {
    asm volatile("cp.async.cg.shared.global [%0], [%1], 16;" :: "r"(dst), "l"(src));
}
#define CP_COMMIT() asm volatile("cp.async.commit_group;" ::: "memory")
#define CP_WAIT(n)  asm volatile("cp.async.wait_group %0;" :: "n"(n) : "memory")

__device__ __forceinline__ void ldsm_x4(uint32_t& r0, uint32_t& r1,
                                        uint32_t& r2, uint32_t& r3, uint32_t addr) {
    asm volatile("ldmatrix.sync.aligned.m8n8.x4.shared.b16 {%0,%1,%2,%3}, [%4];"
                 : "=r"(r0), "=r"(r1), "=r"(r2), "=r"(r3) : "r"(addr));
}

__device__ __forceinline__ void mma16816(float* d, const uint32_t* a,
                                         uint32_t b0, uint32_t b1) {
    asm volatile(
        "mma.sync.aligned.m16n8k16.row.col.f32.f16.f16.f32 "
        "{%0,%1,%2,%3}, {%4,%5,%6,%7}, {%8,%9}, {%0,%1,%2,%3};"
        : "+f"(d[0]), "+f"(d[1]), "+f"(d[2]), "+f"(d[3])
        : "r"(a[0]), "r"(a[1]), "r"(a[2]), "r"(a[3]), "r"(b0), "r"(b1));
}

// sigmoid via single-MUFU tanh.approx: sig(v) = 0.5*tanh(0.5v) + 0.5
__device__ __forceinline__ float fsig(float v) {
    float t;
    asm("tanh.approx.f32 %0, %1;" : "=f"(t) : "f"(v * 0.5f));
    return fmaf(0.5f, t, 0.5f);
}

// ============================ merged pre-pass ============================
__global__ void prepass_kernel(const float* __restrict__ x,
                               const float* __restrict__ W) {
    if (blockIdx.x < NC_BLOCKS) {
        size_t i = ((size_t)blockIdx.x * 256 + threadIdx.x) * 8;
        float4 f0 = *reinterpret_cast<const float4*>(x + i);
        float4 f1 = *reinterpret_cast<const float4*>(x + i + 4);
        __half2 h0 = __floats2half2_rn(f0.x, f0.y);
        __half2 h1 = __floats2half2_rn(f0.z, f0.w);
        __half2 h2 = __floats2half2_rn(f1.x, f1.y);
        __half2 h3 = __floats2half2_rn(f1.z, f1.w);
        uint4 o;
        o.x = *reinterpret_cast<uint32_t*>(&h0);
        o.y = *reinterpret_cast<uint32_t*>(&h1);
        o.z = *reinterpret_cast<uint32_t*>(&h2);
        o.w = *reinterpret_cast<uint32_t*>(&h3);
        *reinterpret_cast<uint4*>(&g_xh[i]) = o;
    } else {
        __shared__ float t[32][33];
        int bidx = blockIdx.x - NC_BLOCKS;
        int bx = bidx & 31;        // n tile
        int by = bidx >> 5;        // k tile
        int tx = threadIdx.x & 31;
        int ty = threadIdx.x >> 5; // 0..7
        int n = bx * 32 + tx;
        int k = by * 32 + ty;
#pragma unroll
        for (int i = 0; i < 4; ++i)
            t[ty + i * 8][tx] = W[(size_t)(k + i * 8) * N_DIM + n];
        __syncthreads();
        int n2 = bx * 32 + ty;
        int k2 = by * 32 + tx;
#pragma unroll
        for (int i = 0; i < 4; ++i)
            g_Wt[(size_t)(n2 + i * 8) * K_DIM + k2] =
                __float2half(t[tx][ty + i * 8]);
    }
}

// ============================ main fused kernel ============================
// 4 warps in 2x2, warp tile 64x64 (acc 128 regs); 3 CTAs/SM (12 warps),
// 2-stage pipeline, 64KB smem/CTA. B fragments HALF-streamed: two ldsm.x4
// quads live (8 regs) per half-iteration, each covering 16 mma — enough
// lookahead to hide LDS latency without exceeding the 170-reg cap.
// Mandatory live set ~= acc 128 + A 16 + B 8 + addressing ~12 = 164.
__global__ __launch_bounds__(THREADS, 3)
void fused_gemm_gn_swish_kernel(const float* __restrict__ bias,
                                const float* __restrict__ mw,
                                float* __restrict__ out) {
    extern __shared__ char smem[];
    uint32_t sb = smem_u32(smem);
    const int tid  = threadIdx.x;
    const int lane = tid & 31;
    const int wid  = tid >> 5;
    const int wm   = wid >> 1;   // 0..1  (M warp row, 64 rows)
    const int wn   = wid & 1;    // 0..1  (N warp col, 64 cols = two GN groups)
    const int m0   = blockIdx.y * BM;
    const int n0   = blockIdx.x * BN;

    uint32_t sA = sb;                      // 2 x 16KB
    uint32_t sB = sb + 2 * A_STAGE;        // 2 x 16KB

    // ---- load addressing: base offsets; chunk i adds immediates ----
    const int r0 = tid >> 3, c0 = tid & 7;
    const uint32_t s_off = (uint32_t)(r0 * 128 + (((c0 ^ (r0 & 7))) << 4));
    const uint32_t g_off = (uint32_t)(r0 * K_DIM + c0 * 8);

    const __half* ag = g_xh + (size_t)m0 * K_DIM + g_off;
    const __half* bg = g_Wt + (size_t)n0 * K_DIM + g_off;

    // prologue: fill stage 0 (A: 8 chunks of 16 rows; B: 8 chunks)
#pragma unroll
    for (int i = 0; i < 8; ++i) cp_async16(sA + s_off + i * 2048, ag + i * 16 * K_DIM);
#pragma unroll
    for (int i = 0; i < 8; ++i) cp_async16(sB + s_off + i * 2048, bg + i * 16 * K_DIM);
    CP_COMMIT();
    ag += BK; bg += BK;

    float acc[4][8][4];
#pragma unroll
    for (int i = 0; i < 4; ++i)
#pragma unroll
        for (int j = 0; j < 8; ++j)
#pragma unroll
            for (int e = 0; e < 4; ++e) acc[i][j][e] = 0.0f;

    // ldmatrix lane addressing
    const int lrow   = lane & 15;
    const int lchunk = lane >> 4;
    const uint32_t aRow = (uint32_t)(wm * 64 + lrow) * 128;
    const uint32_t bRow = (uint32_t)(wn * 64 + lrow) * 128;
    uint32_t soff[4];
#pragma unroll
    for (int ks = 0; ks < 4; ++ks)
        soff[ks] = (uint32_t)(((ks * 2 + lchunk) ^ (lrow & 7)) << 4);

    for (int kt = 0; kt < KTILES; ++kt) {
        CP_WAIT(0);          // stage kt resident
        __syncthreads();     // other buffer free; loads visible

        // issue stage kt+1 into the other buffer
        if (kt + 1 < KTILES) {
            uint32_t dA = sA + ((kt + 1) & 1) * A_STAGE + s_off;
            uint32_t dB = sB + ((kt + 1) & 1) * B_STAGE + s_off;
#pragma unroll
            for (int i = 0; i < 8; ++i) cp_async16(dA + i * 2048, ag + i * 16 * K_DIM);
#pragma unroll
            for (int i = 0; i < 8; ++i) cp_async16(dB + i * 2048, bg + i * 16 * K_DIM);
            CP_COMMIT();
            ag += BK; bg += BK;
        }

        uint32_t aB = sA + (kt & 1) * A_STAGE + aRow;
        uint32_t bB = sB + (kt & 1) * B_STAGE + bRow;
#pragma unroll
        for (int ks = 0; ks < 4; ++ks) {
            // A fragments resident for this ks (16 regs)
            uint32_t a[4][4];
#pragma unroll
            for (int mi = 0; mi < 4; ++mi)
                ldsm_x4(a[mi][0], a[mi][1], a[mi][2], a[mi][3],
                        aB + mi * (16 * 128) + soff[ks]);
            // B half-streamed: 2 quads (8 regs) live per half, 16 mma each
#pragma unroll
            for (int h = 0; h < 2; ++h) {
                uint32_t b[2][4];
#pragma unroll
                for (int pp = 0; pp < 2; ++pp)
                    ldsm_x4(b[pp][0], b[pp][1], b[pp][2], b[pp][3],
                            bB + (2 * h + pp) * (16 * 128) + soff[ks]);
                // b[pp][0]=n(lo8) k0-7, [1]=n(hi8) k0-7, [2]=lo k8-15, [3]=hi k8-15
#pragma unroll
                for (int mi = 0; mi < 4; ++mi) {
#pragma unroll
                    for (int nj = 0; nj < 4; ++nj) {
                        int ni = 4 * h + nj;
                        uint32_t b0 = (nj & 1) ? b[nj >> 1][1] : b[nj >> 1][0];
                        uint32_t b1 = (nj & 1) ? b[nj >> 1][3] : b[nj >> 1][2];
                        mma16816(acc[mi][ni], a[mi], b0, b1);
                    }
                }
            }
        }
    }

    // -------- fused epilogue: bias + GroupNorm(32ch) + swish * w * swish --------
    const int q  = lane >> 2;
    const int qt = lane & 3;
    const float inv32 = 1.0f / 32.0f;
    const float* bp = bias + n0 + wn * 64 + qt * 2;
    const float* wp = mw   + n0 + wn * 64 + qt * 2;

#pragma unroll
    for (int mi = 0; mi < 4; ++mi) {
#pragma unroll
        for (int half = 0; half < 2; ++half) {
            int row = m0 + wm * 64 + mi * 16 + half * 8 + q;
            float* op = out + (size_t)row * N_DIM + n0 + wn * 64;
#pragma unroll
            for (int g2 = 0; g2 < 2; ++g2) {     // two 32-ch groups per warp tile
                float v[8];
                float sum = 0.0f, ssq = 0.0f;
#pragma unroll
                for (int nj = 0; nj < 4; ++nj) {
                    int ni = g2 * 4 + nj;
                    float2 bv = *reinterpret_cast<const float2*>(bp + ni * 8);
#pragma unroll
                    for (int e = 0; e < 2; ++e) {
                        float val = acc[mi][ni][half * 2 + e] + ((e == 0) ? bv.x : bv.y);
                        v[nj * 2 + e] = val;
                        sum += val;
                        ssq = fmaf(val, val, ssq);
                    }
                }
                sum += __shfl_xor_sync(0xffffffffu, sum, 1);
                ssq += __shfl_xor_sync(0xffffffffu, ssq, 1);
                sum += __shfl_xor_sync(0xffffffffu, sum, 2);
                ssq += __shfl_xor_sync(0xffffffffu, ssq, 2);
                float mean = sum * inv32;
                float var  = fmaf(ssq, inv32, -mean * mean);
                float rstd = rsqrtf(var + 1e-5f);

#pragma unroll
                for (int nj = 0; nj < 4; ++nj) {
                    int ni = g2 * 4 + nj;
                    float2 wv = *reinterpret_cast<const float2*>(wp + ni * 8);
                    float2 o;
#pragma unroll
                    for (int e = 0; e < 2; ++e) {
                        float nv = (v[nj * 2 + e] - mean) * rstd;
                        float s  = nv * fsig(nv);
                        float mm = s * ((e == 0) ? wv.x : wv.y);
                        float ov = mm * fsig(mm);
                        if (e == 0) o.x = ov; else o.y = ov;
                    }
                    __stcs(reinterpret_cast<float2*>(op + ni * 8 + qt * 2), o);
                }
            }
        }
    }
}

// ============================ launch ============================
extern "C" void kernel_launch(void* const* d_in, const int* in_sizes, int n_in,
                              void* d_out, int out_size) {
    const float* x  = (const float*)d_in[0];
    const float* W  = (const float*)d_in[1];
    const float* b  = (const float*)d_in[2];
    const float* mw = (const float*)d_in[3];
    float* out = (float*)d_out;

    const size_t M = (size_t)in_sizes[0] / K_DIM;   // 65536

    // 1) merged pre-pass: x -> fp16 and W -> Wt fp16
    prepass_kernel<<<NC_BLOCKS + (N_DIM / 32) * (K_DIM / 32), 256>>>(x, W);

    // 2) fused GEMM + bias + GroupNorm + Swish chain (3 CTAs/SM, half-streamed B)
    cudaFuncSetAttribute(fused_gemm_gn_swish_kernel,
                         cudaFuncAttributeMaxDynamicSharedMemorySize, SMEM_TOTAL);
    dim3 grid(N_DIM / BN, (unsigned)(M / BM));  // x fastest: 8 N-tiles share an A band in L2
    fused_gemm_gn_swish_kernel<<<grid, THREADS, SMEM_TOTAL>>>(b, mw, out);
}

// round 14
// speedup vs baseline: 1.2440x; 1.0593x over previous
#include <cuda_runtime.h>
#include <cuda_fp16.h>
#include <cstdint>

// ============================ config ============================
#define K_DIM 1024
#define N_DIM 1024
#define BM 128
#define BN 128
#define BK 64
#define KTILES (K_DIM / BK)   // 16
#define NSTAGE 3
#define THREADS 256

#define A_STAGE (BM * BK * 2)                      // 16384 B
#define B_STAGE (BN * BK * 2)                      // 16384 B
#define SMEM_TOTAL (NSTAGE * (A_STAGE + B_STAGE))  // 98304 B (3-stage)

#define NC_BLOCKS 32768   // convert blocks in prepass (65536*1024/8/256)

// static scratch (allocation-free rule: __device__ globals)
__device__ __half g_xh[(size_t)65536 * K_DIM];   // x converted to fp16
__device__ __half g_Wt[(size_t)N_DIM * K_DIM];   // W transposed to (N,K) fp16

// ============================ helpers ============================
__device__ __forceinline__ uint32_t smem_u32(const void* p) {
    uint32_t a;
    asm("{ .reg .u64 t; cvta.to.shared.u64 t, %1; cvt.u32.u64 %0, t; }"
        : "=r"(a) : "l"(p));
    return a;
}

__device__ __forceinline__ void cp_async16(uint32_t dst, const void* src) {
    asm volatile("cp.async.cg.shared.global [%0], [%1], 16;" :: "r"(dst), "l"(src));
}
#define CP_COMMIT() asm volatile("cp.async.commit_group;" ::: "memory")
#define CP_WAIT(n)  asm volatile("cp.async.wait_group %0;" :: "n"(n) : "memory")

__device__ __forceinline__ void ldsm_x4(uint32_t& r0, uint32_t& r1,
                                        uint32_t& r2, uint32_t& r3, uint32_t addr) {
    asm volatile("ldmatrix.sync.aligned.m8n8.x4.shared.b16 {%0,%1,%2,%3}, [%4];"
                 : "=r"(r0), "=r"(r1), "=r"(r2), "=r"(r3) : "r"(addr));
}

__device__ __forceinline__ void mma16816(float* d, const uint32_t* a,
                                         uint32_t b0, uint32_t b1) {
    asm volatile(
        "mma.sync.aligned.m16n8k16.row.col.f32.f16.f16.f32 "
        "{%0,%1,%2,%3}, {%4,%5,%6,%7}, {%8,%9}, {%0,%1,%2,%3};"
        : "+f"(d[0]), "+f"(d[1]), "+f"(d[2]), "+f"(d[3])
        : "r"(a[0]), "r"(a[1]), "r"(a[2]), "r"(a[3]), "r"(b0), "r"(b1));
}

// sigmoid via single-MUFU tanh.approx: sig(v) = 0.5*tanh(0.5v) + 0.5
__device__ __forceinline__ float fsig(float v) {
    float t;
    asm("tanh.approx.f32 %0, %1;" : "=f"(t) : "f"(v * 0.5f));
    return fmaf(0.5f, t, 0.5f);
}

// ============================ merged pre-pass ============================
__global__ void prepass_kernel(const float* __restrict__ x,
                               const float* __restrict__ W) {
    if (blockIdx.x < NC_BLOCKS) {
        size_t i = ((size_t)blockIdx.x * 256 + threadIdx.x) * 8;
        float4 f0 = *reinterpret_cast<const float4*>(x + i);
        float4 f1 = *reinterpret_cast<const float4*>(x + i + 4);
        __half2 h0 = __floats2half2_rn(f0.x, f0.y);
        __half2 h1 = __floats2half2_rn(f0.z, f0.w);
        __half2 h2 = __floats2half2_rn(f1.x, f1.y);
        __half2 h3 = __floats2half2_rn(f1.z, f1.w);
        uint4 o;
        o.x = *reinterpret_cast<uint32_t*>(&h0);
        o.y = *reinterpret_cast<uint32_t*>(&h1);
        o.z = *reinterpret_cast<uint32_t*>(&h2);
        o.w = *reinterpret_cast<uint32_t*>(&h3);
        *reinterpret_cast<uint4*>(&g_xh[i]) = o;
    } else {
        __shared__ float t[32][33];
        int bidx = blockIdx.x - NC_BLOCKS;
        int bx = bidx & 31;        // n tile
        int by = bidx >> 5;        // k tile
        int tx = threadIdx.x & 31;
        int ty = threadIdx.x >> 5; // 0..7
        int n = bx * 32 + tx;
        int k = by * 32 + ty;
#pragma unroll
        for (int i = 0; i < 4; ++i)
            t[ty + i * 8][tx] = W[(size_t)(k + i * 8) * N_DIM + n];
        __syncthreads();
        int n2 = bx * 32 + ty;
        int k2 = by * 32 + tx;
#pragma unroll
        for (int i = 0; i < 4; ++i)
            g_Wt[(size_t)(n2 + i * 8) * K_DIM + k2] =
                __float2half(t[tx][ty + i * 8]);
    }
}

// ============================ main fused kernel ============================
// 8 warps in 2(M)x4(N), warp tile 64x32 (acc 64 regs); 2 CTAs/SM (16 warps),
// 3-stage pipeline, 96KB smem/CTA. This shape minimizes LSU-ISSUE per tensor
// cycle (LDGSTS 512 + LDSM 768 = 1280 cyc vs 1024 tensor cyc per CTA-ktile),
// vs 1.5 ratio in the BN=64 config — LSU issue is the measured binding pipe.
__global__ __launch_bounds__(THREADS, 2)
void fused_gemm_gn_swish_kernel(const float* __restrict__ bias,
                                const float* __restrict__ mw,
                                float* __restrict__ out) {
    extern __shared__ char smem[];
    uint32_t sb = smem_u32(smem);
    const int tid  = threadIdx.x;
    const int lane = tid & 31;
    const int wid  = tid >> 5;
    const int wm   = wid >> 2;   // 0..1  (M warp row, 64 rows)
    const int wn   = wid & 3;    // 0..3  (N warp col, 32 cols = one GN group)
    const int m0   = blockIdx.y * BM;
    const int n0   = blockIdx.x * BN;

    uint32_t sA = sb;                        // 3 x 16KB
    uint32_t sB = sb + NSTAGE * A_STAGE;     // 3 x 16KB

    // ---- load addressing: base offsets; chunk i adds immediates ----
    // 256 threads: 4 chunks A (rows tid>>3 + 32i), 4 chunks B
    const int r0 = tid >> 3, c0 = tid & 7;
    const uint32_t s_off = (uint32_t)(r0 * 128 + (((c0 ^ (r0 & 7))) << 4));
    const uint32_t g_off = (uint32_t)(r0 * K_DIM + c0 * 8);

    const __half* ag = g_xh + (size_t)m0 * K_DIM + g_off;
    const __half* bg = g_Wt + (size_t)n0 * K_DIM + g_off;

    // prologue: fill stages 0,1
#pragma unroll
    for (int s = 0; s < 2; ++s) {
        uint32_t dA = sA + s * A_STAGE + s_off, dB = sB + s * B_STAGE + s_off;
#pragma unroll
        for (int i = 0; i < 4; ++i) cp_async16(dA + i * 4096, ag + i * 32 * K_DIM);
#pragma unroll
        for (int i = 0; i < 4; ++i) cp_async16(dB + i * 4096, bg + i * 32 * K_DIM);
        CP_COMMIT();
        ag += BK; bg += BK;
    }

    float acc[4][4][4];
#pragma unroll
    for (int i = 0; i < 4; ++i)
#pragma unroll
        for (int j = 0; j < 4; ++j)
#pragma unroll
            for (int e = 0; e < 4; ++e) acc[i][j][e] = 0.0f;

    // ldmatrix lane addressing
    const int lrow   = lane & 15;
    const int lchunk = lane >> 4;
    const uint32_t aRow = (uint32_t)(wm * 64 + lrow) * 128;
    const uint32_t bRow = (uint32_t)(wn * 32 + lrow) * 128;
    uint32_t soff[4];
#pragma unroll
    for (int ks = 0; ks < 4; ++ks)
        soff[ks] = (uint32_t)(((ks * 2 + lchunk) ^ (lrow & 7)) << 4);

    int buf = 0, ibuf = 2;
    for (int kt = 0; kt < KTILES; ++kt) {
        // 3-stage: stage kt committed 2 iterations ago
        if (kt < KTILES - 1) { CP_WAIT(1); } else { CP_WAIT(0); }
        __syncthreads();

        // issue stage kt+2 (overwrites buffer of kt-1, protected by the sync)
        if (kt + 2 < KTILES) {
            uint32_t dA = sA + ibuf * A_STAGE + s_off;
            uint32_t dB = sB + ibuf * B_STAGE + s_off;
#pragma unroll
            for (int i = 0; i < 4; ++i) cp_async16(dA + i * 4096, ag + i * 32 * K_DIM);
#pragma unroll
            for (int i = 0; i < 4; ++i) cp_async16(dB + i * 4096, bg + i * 32 * K_DIM);
            CP_COMMIT();
            ag += BK; bg += BK;
            if (++ibuf == NSTAGE) ibuf = 0;
        }

        uint32_t aB = sA + buf * A_STAGE + aRow;
        uint32_t bB = sB + buf * B_STAGE + bRow;
#pragma unroll
        for (int ks = 0; ks < 4; ++ks) {
            uint32_t a[4][4], b[2][4];
#pragma unroll
            for (int mi = 0; mi < 4; ++mi)
                ldsm_x4(a[mi][0], a[mi][1], a[mi][2], a[mi][3],
                        aB + mi * (16 * 128) + soff[ks]);
#pragma unroll
            for (int p = 0; p < 2; ++p)
                ldsm_x4(b[p][0], b[p][1], b[p][2], b[p][3],
                        bB + p * (16 * 128) + soff[ks]);
            // b[p][0]=n(lo8,p) k0-7, b[p][1]=n(hi8,p) k0-7, b[p][2]=lo k8-15, b[p][3]=hi k8-15
#pragma unroll
            for (int mi = 0; mi < 4; ++mi) {
#pragma unroll
                for (int ni = 0; ni < 4; ++ni) {
                    uint32_t b0 = (ni & 1) ? b[ni >> 1][1] : b[ni >> 1][0];
                    uint32_t b1 = (ni & 1) ? b[ni >> 1][3] : b[ni >> 1][2];
                    mma16816(acc[mi][ni], a[mi], b0, b1);
                }
            }
        }
        if (++buf == NSTAGE) buf = 0;
    }

    // -------- fused epilogue: bias + GroupNorm(32ch) + swish * w * swish --------
    // Warp covers exactly one 32-channel group: quad shfl reduce (xor 1,2).
    const int q  = lane >> 2;
    const int qt = lane & 3;
    const float inv32 = 1.0f / 32.0f;
    const float* bp = bias + n0 + wn * 32 + qt * 2;
    const float* wp = mw   + n0 + wn * 32 + qt * 2;

#pragma unroll
    for (int mi = 0; mi < 4; ++mi) {
#pragma unroll
        for (int half = 0; half < 2; ++half) {
            int row = m0 + wm * 64 + mi * 16 + half * 8 + q;
            float* op = out + (size_t)row * N_DIM + n0 + wn * 32;

            float v[8];
            float sum = 0.0f, ssq = 0.0f;
#pragma unroll
            for (int ni = 0; ni < 4; ++ni) {
                float2 bv = *reinterpret_cast<const float2*>(bp + ni * 8);
#pragma unroll
                for (int e = 0; e < 2; ++e) {
                    float val = acc[mi][ni][half * 2 + e] + ((e == 0) ? bv.x : bv.y);
                    v[ni * 2 + e] = val;
                    sum += val;
                    ssq = fmaf(val, val, ssq);
                }
            }
            sum += __shfl_xor_sync(0xffffffffu, sum, 1);
            ssq += __shfl_xor_sync(0xffffffffu, ssq, 1);
            sum += __shfl_xor_sync(0xffffffffu, sum, 2);
            ssq += __shfl_xor_sync(0xffffffffu, ssq, 2);
            float mean = sum * inv32;
            float var  = fmaf(ssq, inv32, -mean * mean);
            float rstd = rsqrtf(var + 1e-5f);

#pragma unroll
            for (int ni = 0; ni < 4; ++ni) {
                float2 wv = *reinterpret_cast<const float2*>(wp + ni * 8);
                float2 o;
#pragma unroll
                for (int e = 0; e < 2; ++e) {
                    float nv = (v[ni * 2 + e] - mean) * rstd;
                    float s  = nv * fsig(nv);
                    float mm = s * ((e == 0) ? wv.x : wv.y);
                    float ov = mm * fsig(mm);
                    if (e == 0) o.x = ov; else o.y = ov;
                }
                __stcs(reinterpret_cast<float2*>(op + ni * 8 + qt * 2), o);
            }
        }
    }
}

// ============================ launch ============================
extern "C" void kernel_launch(void* const* d_in, const int* in_sizes, int n_in,
                              void* d_out, int out_size) {
    const float* x  = (const float*)d_in[0];
    const float* W  = (const float*)d_in[1];
    const float* b  = (const float*)d_in[2];
    const float* mw = (const float*)d_in[3];
    float* out = (float*)d_out;

    const size_t M = (size_t)in_sizes[0] / K_DIM;   // 65536

    // 1) merged pre-pass: x -> fp16 and W -> Wt fp16
    prepass_kernel<<<NC_BLOCKS + (N_DIM / 32) * (K_DIM / 32), 256>>>(x, W);

    // 2) fused GEMM + bias + GroupNorm + Swish chain (2 CTAs/SM, 16 warps)
    cudaFuncSetAttribute(fused_gemm_gn_swish_kernel,
                         cudaFuncAttributeMaxDynamicSharedMemorySize, SMEM_TOTAL);
    dim3 grid(N_DIM / BN, (unsigned)(M / BM));  // x fastest: 8 N-tiles share an A band in L2
    fused_gemm_gn_swish_kernel<<<grid, THREADS, SMEM_TOTAL>>>(b, mw, out);
}